// round 15
// baseline (speedup 1.0000x reference)
#include <cuda_runtime.h>
#include <cuda_fp16.h>
#include <cstdint>

#define BATCH 8
#define SEQ   2048
#define HID   1024
#define M_TOT (BATCH * SEQ)        // 16384
#define WHALF 64
#define NEG_INF -1e9f

// Scratch (__device__ globals; no allocation allowed) — all fp16 hi/lo splits
__device__ __align__(16) __half g_qw_hi[(size_t)M_TOT * HID];
__device__ __align__(16) __half g_qw_lo[(size_t)M_TOT * HID];
__device__ __align__(16) __half g_a_hi[(size_t)M_TOT * HID];   // also V in phase 3
__device__ __align__(16) __half g_a_lo[(size_t)M_TOT * HID];
__device__ __align__(16) __half g_wt_hi[(size_t)HID * HID];
__device__ __align__(16) __half g_wt_lo[(size_t)HID * HID];

// ---------------------------------------------------------------------------
// PTX helpers (architecture-neutral, sm_80-level)
// ---------------------------------------------------------------------------
__device__ __forceinline__ uint32_t smem_u32(const void* p) {
    uint32_t a;
    asm("{ .reg .u64 t; cvta.to.shared.u64 t, %1; cvt.u32.u64 %0, t; }" : "=r"(a) : "l"(p));
    return a;
}

#define CP_ASYNC16(dst_u32, src_ptr) \
    asm volatile("cp.async.cg.shared.global [%0], [%1], 16;" :: "r"(dst_u32), "l"(src_ptr))
#define CP_COMMIT() asm volatile("cp.async.commit_group;" ::: "memory")
#define CP_WAIT(n)  asm volatile("cp.async.wait_group %0;" :: "n"(n) : "memory")

#define LDMATRIX_X4(r0, r1, r2, r3, addr) \
    asm volatile("ldmatrix.sync.aligned.m8n8.x4.shared.b16 {%0,%1,%2,%3}, [%4];" \
                 : "=r"(r0), "=r"(r1), "=r"(r2), "=r"(r3) : "r"(addr))
#define LDMATRIX_X4_TRANS(r0, r1, r2, r3, addr) \
    asm volatile("ldmatrix.sync.aligned.m8n8.x4.trans.shared.b16 {%0,%1,%2,%3}, [%4];" \
                 : "=r"(r0), "=r"(r1), "=r"(r2), "=r"(r3) : "r"(addr))

#define MMA_F16(d, a, b0v, b1v) \
    asm volatile("mma.sync.aligned.m16n8k16.row.col.f32.f16.f16.f32 " \
                 "{%0,%1,%2,%3},{%4,%5,%6,%7},{%8,%9},{%0,%1,%2,%3};" \
                 : "+f"((d)[0]), "+f"((d)[1]), "+f"((d)[2]), "+f"((d)[3]) \
                 : "r"((a)[0]), "r"((a)[1]), "r"((a)[2]), "r"((a)[3]), \
                   "r"(b0v), "r"(b1v))

__device__ __forceinline__ void split_pack_h(float a, float b, uint32_t& hi, uint32_t& lo) {
    __half ha = __float2half_rn(a);
    __half hb = __float2half_rn(b);
    __half la = __float2half_rn(a - __half2float(ha));
    __half lb = __float2half_rn(b - __half2float(hb));
    __half hp[2] = {ha, hb};
    __half lp[2] = {la, lb};
    hi = *(uint32_t*)hp;
    lo = *(uint32_t*)lp;
}

// ---------------------------------------------------------------------------
// Prep 1: repr -> a_hi/a_lo (fp16)
// ---------------------------------------------------------------------------
__global__ __launch_bounds__(256) void repr_split_kernel(const float* __restrict__ r) {
    size_t i = ((size_t)blockIdx.x * 256 + threadIdx.x) * 4;
    float4 v = *(const float4*)&r[i];
    uint32_t h0, l0, h1, l1;
    split_pack_h(v.x, v.y, h0, l0);
    split_pack_h(v.z, v.w, h1, l1);
    uint2 hh = {h0, h1}, ll = {l0, l1};
    *(uint2*)&g_a_hi[i] = hh;
    *(uint2*)&g_a_lo[i] = ll;
}

// ---------------------------------------------------------------------------
// Prep 2: W[k][n] -> Wt_hi/Wt_lo [n][k] (fp16)
// ---------------------------------------------------------------------------
__global__ void wt_split_kernel(const float* __restrict__ W) {
    __shared__ float t[32][33];
    int bx = blockIdx.x * 32, by = blockIdx.y * 32;
    int x = threadIdx.x, y0 = threadIdx.y;
#pragma unroll
    for (int i = 0; i < 32; i += 8)
        t[y0 + i][x] = W[(size_t)(by + y0 + i) * HID + bx + x];
    __syncthreads();
#pragma unroll
    for (int i = 0; i < 32; i += 8) {
        float v = t[x][y0 + i];
        size_t o = (size_t)(bx + y0 + i) * HID + by + x;
        __half hi = __float2half_rn(v);
        g_wt_hi[o] = hi;
        g_wt_lo[o] = __float2half_rn(v - __half2float(hi));
    }
}

// ---------------------------------------------------------------------------
// Kernel 1: PERSISTENT fp16x3 GEMM — 296 CTAs loop over 1024 tiles; next
// tile's first chunk is prefetched during the current tile's last chunk.
// ---------------------------------------------------------------------------
#define KB   32
#define NCH  (HID / KB)
#define TPCH 40
#define TILE_B  (128 * TPCH * 2)
#define STAGE_B (4 * TILE_B)
#define GEMM_SMEM (2 * STAGE_B)
#define NTILES  ((M_TOT / 128) * (HID / 128))   // 1024
#define GEMM_GRID 296

__global__ __launch_bounds__(256, 2) void gemm_f16x3_kernel() {
    extern __shared__ char sm[];
    const uint32_t smBase = smem_u32(sm);

    const int tid  = threadIdx.x;
    const int w    = tid >> 5;
    const int lane = tid & 31;
    const int wm   = w & 1;
    const int wn   = w >> 1;
    const int gid  = lane >> 2, tig = lane & 3;

    // per-thread loader geometry (tile-invariant)
    const int r0 = tid >> 2,          s0 = tid & 3;
    const int r1 = (tid + 256) >> 2,  s1 = (tid + 256) & 3;
    const uint32_t o0 = (uint32_t)(r0 * (TPCH * 2) + s0 * 16);
    const uint32_t o1 = (uint32_t)(r1 * (TPCH * 2) + s1 * 16);

    const __half *pah0, *pal0, *pah1, *pal1, *pbh0, *pbl0, *pbh1, *pbl1;
    auto set_ptrs = [&](int t) {
        const int m0 = (t >> 3) * 128, n0 = (t & 7) * 128;
        size_t ia0 = (size_t)(m0 + r0) * HID + s0 * 8;
        size_t ia1 = (size_t)(m0 + r1) * HID + s1 * 8;
        size_t ib0 = (size_t)(n0 + r0) * HID + s0 * 8;
        size_t ib1 = (size_t)(n0 + r1) * HID + s1 * 8;
        pah0 = g_a_hi + ia0;  pal0 = g_a_lo + ia0;
        pah1 = g_a_hi + ia1;  pal1 = g_a_lo + ia1;
        pbh0 = g_wt_hi + ib0; pbl0 = g_wt_lo + ib0;
        pbh1 = g_wt_hi + ib1; pbl1 = g_wt_lo + ib1;
    };
    auto load_chunk = [&](uint32_t sb) {
        CP_ASYNC16(sb + o0,              pah0);
        CP_ASYNC16(sb + TILE_B + o0,     pal0);
        CP_ASYNC16(sb + 2 * TILE_B + o0, pbh0);
        CP_ASYNC16(sb + 3 * TILE_B + o0, pbl0);
        CP_ASYNC16(sb + o1,              pah1);
        CP_ASYNC16(sb + TILE_B + o1,     pal1);
        CP_ASYNC16(sb + 2 * TILE_B + o1, pbh1);
        CP_ASYNC16(sb + 3 * TILE_B + o1, pbl1);
        pah0 += KB; pal0 += KB; pbh0 += KB; pbl0 += KB;
        pah1 += KB; pal1 += KB; pbh1 += KB; pbl1 += KB;
    };

    // prologue: first tile's chunk 0
    set_ptrs(blockIdx.x);
    load_chunk(smBase);
    CP_COMMIT();

    for (int t = blockIdx.x; t < NTILES; t += GEMM_GRID) {
        const int m0 = (t >> 3) * 128, n0 = (t & 7) * 128;

        float acc[4][4][4];
#pragma unroll
        for (int i = 0; i < 4; i++)
#pragma unroll
            for (int j = 0; j < 4; j++)
#pragma unroll
                for (int q = 0; q < 4; q++) acc[i][j][q] = 0.f;

        for (int c = 0; c < NCH; c++) {
            CP_WAIT(0);
            __syncthreads();
            if (c + 1 < NCH) {
                load_chunk(smBase + (uint32_t)(((c + 1) & 1) * STAGE_B));
                CP_COMMIT();
            } else if (t + GEMM_GRID < NTILES) {
                // prefetch next tile's chunk 0 into buffer 0 (free now)
                set_ptrs(t + GEMM_GRID);
                load_chunk(smBase);
                CP_COMMIT();
            }

            const uint32_t sb = smBase + (uint32_t)((c & 1) * STAGE_B);
#pragma unroll
            for (int ks = 0; ks < KB; ks += 16) {
                uint32_t ah[4][4], al[4][4], bh[2][4], bl[2][4];
                const uint32_t cofs = (uint32_t)((ks + ((lane >> 4) << 3)) * 2);
#pragma unroll
                for (int mt = 0; mt < 4; mt++) {
                    uint32_t ra = sb + (uint32_t)((wm * 64 + mt * 16 + (lane & 15)) * (TPCH * 2)) + cofs;
                    LDMATRIX_X4(ah[mt][0], ah[mt][1], ah[mt][2], ah[mt][3], ra);
                    LDMATRIX_X4(al[mt][0], al[mt][1], al[mt][2], al[mt][3], ra + TILE_B);
                }
#pragma unroll
                for (int np = 0; np < 2; np++) {
                    uint32_t rb = sb + 2 * TILE_B +
                                  (uint32_t)((wn * 32 + np * 16 + (lane & 15)) * (TPCH * 2)) + cofs;
                    LDMATRIX_X4(bh[np][0], bh[np][1], bh[np][2], bh[np][3], rb);
                    LDMATRIX_X4(bl[np][0], bl[np][1], bl[np][2], bl[np][3], rb + TILE_B);
                }
#pragma unroll
                for (int mt = 0; mt < 4; mt++)
#pragma unroll
                    for (int nt = 0; nt < 4; nt++) {
                        const int np = nt >> 1, hp = nt & 1;
                        MMA_F16(acc[mt][nt], ah[mt], bh[np][hp], bh[np][hp + 2]);
                    }
#pragma unroll
                for (int mt = 0; mt < 4; mt++)
#pragma unroll
                    for (int nt = 0; nt < 4; nt++) {
                        const int np = nt >> 1, hp = nt & 1;
                        MMA_F16(acc[mt][nt], ah[mt], bl[np][hp], bl[np][hp + 2]);
                    }
#pragma unroll
                for (int mt = 0; mt < 4; mt++)
#pragma unroll
                    for (int nt = 0; nt < 4; nt++) {
                        const int np = nt >> 1, hp = nt & 1;
                        MMA_F16(acc[mt][nt], al[mt], bh[np][hp], bh[np][hp + 2]);
                    }
            }
        }

        // epilogue (smem-free; overlaps the prefetched next-tile loads)
#pragma unroll
        for (int mt = 0; mt < 4; mt++) {
#pragma unroll
            for (int nt = 0; nt < 4; nt++) {
#pragma unroll
                for (int h = 0; h < 2; h++) {
                    int r  = m0 + wm * 64 + mt * 16 + gid + h * 8;
                    int cc = n0 + wn * 32 + nt * 8 + tig * 2;
                    uint32_t hp2, lp2;
                    split_pack_h(acc[mt][nt][h * 2 + 0], acc[mt][nt][h * 2 + 1], hp2, lp2);
                    *(uint32_t*)&g_qw_hi[(size_t)r * HID + cc] = hp2;
                    *(uint32_t*)&g_qw_lo[(size_t)r * HID + cc] = lp2;
                }
            }
        }
    }
}

// ---------------------------------------------------------------------------
// Kernel 2: tensor-core windowed attention — 64-query / 128-thread CTAs,
// warp-private bands, occ 2; R13-style inline loaders (lean regs) + V
// stage-0 prefetch during the last phase-1 chunk.
// ---------------------------------------------------------------------------
#define NTHR   128
#define QP     40                   // fp16 smem pitch (80 B rows)
#define QH_B   (64 * QP * 2)        // 5120
#define KH_B   (192 * QP * 2)       // 15360
#define A_STG  (2 * QH_B + 2 * KH_B)  // 40960: Qh | Ql | Kh | Kl
#define DCW 64
#define NDC (HID / DCW)             // 16
#define VP2 72                      // fp16 pitch for 64-col V rows (144 B)
#define V_B2 (192 * VP2 * 2)        // 27648 per stage
#define ATTN_SMEM (2 * A_STG)       // 81920 (V stages at offsets 0 / V_B2)

__global__ __launch_bounds__(NTHR, 2) void attn_tc_kernel(
    const float* __restrict__ repr, float* __restrict__ out)
{
    extern __shared__ char sm[];
    const uint32_t smb = smem_u32(sm);

    const int tid  = threadIdx.x;
    const int wm   = tid >> 5;          // 0..3: row group AND band owner
    const int lane = tid & 31;
    const int gid  = lane >> 2, tig = lane & 3;
    const int bc0  = wm * 16;           // warp's band-col base (rel. to k0)

    const int b  = blockIdx.y;
    const int q0 = blockIdx.x * 64;
    const int k0 = q0 - WHALF;
    const size_t rowbase = (size_t)b * SEQ;

    // ---------------- Phase 1: S = Q·K^T (frags in regs) -----------------
    auto load_qk = [&](int stage, int c) {
        const int kd = c * KB;
        const uint32_t sb = smb + stage * A_STG;
#pragma unroll
        for (int rep = 0; rep < 2; rep++) {          // Q: 64 rows x 4 segs
            int idx = tid + rep * NTHR;
            int row = idx >> 2, seg = idx & 3;
            uint32_t off = (uint32_t)(row * (QP * 2) + seg * 16);
            size_t ga = (rowbase + q0 + row) * HID + kd + seg * 8;
            CP_ASYNC16(sb + off,        &g_qw_hi[ga]);
            CP_ASYNC16(sb + QH_B + off, &g_qw_lo[ga]);
        }
#pragma unroll
        for (int rep = 0; rep < 6; rep++) {          // K: 192 rows x 4 segs
            int idx = tid + rep * NTHR;
            int row = idx >> 2, seg = idx & 3;
            int j = k0 + row;
            j = j < 0 ? 0 : (j >= SEQ ? SEQ - 1 : j);   // clamp; masked later
            uint32_t off = (uint32_t)(row * (QP * 2) + seg * 16);
            size_t ga = (rowbase + j) * HID + kd + seg * 8;
            CP_ASYNC16(sb + 2 * QH_B + off,        &g_a_hi[ga]);
            CP_ASYNC16(sb + 2 * QH_B + KH_B + off, &g_a_lo[ga]);
        }
    };
    auto load_v = [&](int stage, int d) {
        const int d0 = d * DCW;
        const uint32_t sb = smb + stage * V_B2;
#pragma unroll
        for (int rep = 0; rep < 12; rep++) {
            int idx = tid + rep * NTHR;
            int vr = idx >> 3, seg = idx & 7;
            int j = k0 + vr;
            j = j < 0 ? 0 : (j >= SEQ ? SEQ - 1 : j);   // clamp; P=0 there
            uint32_t off = (uint32_t)(vr * (VP2 * 2) + seg * 16);
            CP_ASYNC16(sb + off, &g_a_hi[(rowbase + j) * HID + d0 + seg * 8]);
        }
    };

    float acc[18][4];
#pragma unroll
    for (int i = 0; i < 18; i++)
#pragma unroll
        for (int q = 0; q < 4; q++) acc[i][q] = 0.f;

    load_qk(0, 0);
    CP_COMMIT();

    for (int c = 0; c < NCH; c++) {
        CP_WAIT(0);
        __syncthreads();
        if (c + 1 < NCH) {
            load_qk((c + 1) & 1, c + 1);
            CP_COMMIT();
        } else {
            // prefetch V stage 0 into dead phase-1 stage-0 smem
            load_v(0, 0);
            CP_COMMIT();
        }

        const uint32_t sb = smb + (c & 1) * A_STG;
#pragma unroll
        for (int ks = 0; ks < 2; ks++) {
            const uint32_t cofs = (uint32_t)((ks * 16 + ((lane >> 4) << 3)) * 2);
            uint32_t ah[4], al[4];
            uint32_t ra = sb + (uint32_t)((wm * 16 + (lane & 15)) * (QP * 2)) + cofs;
            LDMATRIX_X4(ah[0], ah[1], ah[2], ah[3], ra);
            LDMATRIX_X4(al[0], al[1], al[2], al[3], ra + QH_B);
#pragma unroll
            for (int p = 0; p < 9; p++) {
                uint32_t bh[4], bl[4];
                uint32_t rb = sb + 2 * QH_B +
                    (uint32_t)((bc0 + p * 16 + (lane & 15)) * (QP * 2)) + cofs;
                LDMATRIX_X4(bh[0], bh[1], bh[2], bh[3], rb);
                LDMATRIX_X4(bl[0], bl[1], bl[2], bl[3], rb + KH_B);
#pragma unroll
                for (int hp = 0; hp < 2; hp++) {
                    int nt = p * 2 + hp;
                    MMA_F16(acc[nt], ah, bh[hp], bh[hp + 2]);
                    MMA_F16(acc[nt], ah, bl[hp], bl[hp + 2]);
                    MMA_F16(acc[nt], al, bh[hp], bh[hp + 2]);
                }
            }
        }
    }

    // ---------------- Phase 2: warp-local softmax -------------------------
#pragma unroll
    for (int nt = 0; nt < 18; nt++) {
#pragma unroll
        for (int h = 0; h < 2; h++) {
            int row = wm * 16 + gid + h * 8;
#pragma unroll
            for (int e = 0; e < 2; e++) {
                int bc = bc0 + nt * 8 + tig * 2 + e;
                int j = k0 + bc, dr = bc - row;
                if (!((j >= 0) && (j < SEQ) && (dr >= 0) && (dr <= 2 * WHALF)))
                    acc[nt][h * 2 + e] = NEG_INF;
            }
        }
    }

    float mrow[2] = {NEG_INF, NEG_INF};
#pragma unroll
    for (int nt = 0; nt < 18; nt++) {
        mrow[0] = fmaxf(mrow[0], fmaxf(acc[nt][0], acc[nt][1]));
        mrow[1] = fmaxf(mrow[1], fmaxf(acc[nt][2], acc[nt][3]));
    }
#pragma unroll
    for (int h = 0; h < 2; h++) {
        mrow[h] = fmaxf(mrow[h], __shfl_xor_sync(0xffffffffu, mrow[h], 1));
        mrow[h] = fmaxf(mrow[h], __shfl_xor_sync(0xffffffffu, mrow[h], 2));
    }

    float srow[2] = {0.f, 0.f};
#pragma unroll
    for (int nt = 0; nt < 18; nt++) {
#pragma unroll
        for (int h = 0; h < 2; h++) {
#pragma unroll
            for (int e = 0; e < 2; e++) {
                float ex = __expf(acc[nt][h * 2 + e] - mrow[h]);
                acc[nt][h * 2 + e] = ex;
                srow[h] += ex;
            }
        }
    }
#pragma unroll
    for (int h = 0; h < 2; h++) {
        srow[h] += __shfl_xor_sync(0xffffffffu, srow[h], 1);
        srow[h] += __shfl_xor_sync(0xffffffffu, srow[h], 2);
    }
    const float inv0 = 1.f / srow[0];
    const float inv1 = 1.f / srow[1];

    // P hi/lo fp16 fragments (9 k-tiles, warp-private band)
    uint32_t ph[9][4], pl[9][4];
#pragma unroll
    for (int t = 0; t < 9; t++) {
        split_pack_h(acc[2 * t][0] * inv0,     acc[2 * t][1] * inv0,     ph[t][0], pl[t][0]);
        split_pack_h(acc[2 * t][2] * inv1,     acc[2 * t][3] * inv1,     ph[t][1], pl[t][1]);
        split_pack_h(acc[2 * t + 1][0] * inv0, acc[2 * t + 1][1] * inv0, ph[t][2], pl[t][2]);
        split_pack_h(acc[2 * t + 1][2] * inv1, acc[2 * t + 1][3] * inv1, ph[t][3], pl[t][3]);
    }

    // ---------------- Phase 3: O = P·V (fp16, 2-term), dc=64 --------------
    for (int d = 0; d < NDC; d++) {
        CP_WAIT(0);
        __syncthreads();
        if (d + 1 < NDC) {
            load_v((d + 1) & 1, d + 1);
            CP_COMMIT();
        }

        const uint32_t vb = smb + (d & 1) * V_B2;

        float o[8][4];
#pragma unroll
        for (int i = 0; i < 8; i++)
#pragma unroll
            for (int q = 0; q < 4; q++) o[i][q] = 0.f;

#pragma unroll
        for (int t = 0; t < 9; t++) {
            const int brow = bc0 + t * 16;
            uint32_t vh[4][4];
#pragma unroll
            for (int p = 0; p < 4; p++) {
                uint32_t rb = vb + (uint32_t)((brow + (lane & 15)) * (VP2 * 2)) +
                              (uint32_t)((p * 16 + ((lane >> 4) << 3)) * 2);
                LDMATRIX_X4_TRANS(vh[p][0], vh[p][1], vh[p][2], vh[p][3], rb);
            }
#pragma unroll
            for (int p = 0; p < 4; p++) {
                MMA_F16(o[p * 2 + 0], ph[t], vh[p][0], vh[p][1]);
                MMA_F16(o[p * 2 + 1], ph[t], vh[p][2], vh[p][3]);
            }
#pragma unroll
            for (int p = 0; p < 4; p++) {
                MMA_F16(o[p * 2 + 0], pl[t], vh[p][0], vh[p][1]);
                MMA_F16(o[p * 2 + 1], pl[t], vh[p][2], vh[p][3]);
            }
        }

        // direct epilogue: out = repr + relu(o)
#pragma unroll
        for (int nt = 0; nt < 8; nt++) {
#pragma unroll
            for (int h = 0; h < 2; h++) {
                int gr = q0 + wm * 16 + gid + h * 8;
                int gc = d * DCW + nt * 8 + tig * 2;
                const float2 rv = *(const float2*)&repr[(rowbase + gr) * HID + gc];
                float2 ov;
                ov.x = rv.x + fmaxf(o[nt][h * 2 + 0], 0.f);
                ov.y = rv.y + fmaxf(o[nt][h * 2 + 1], 0.f);
                *(float2*)&out[(rowbase + gr) * HID + gc] = ov;
            }
        }
    }
}

// ---------------------------------------------------------------------------
extern "C" void kernel_launch(void* const* d_in, const int* in_sizes, int n_in,
                              void* d_out, int out_size)
{
    (void)in_sizes; (void)n_in; (void)out_size;
    const float* repr = (const float*)d_in[0];
    const float* W    = (const float*)d_in[1];
    float* out        = (float*)d_out;

    repr_split_kernel<<<(M_TOT * HID) / (256 * 4), 256>>>(repr);
    dim3 tb(32, 8), tg(HID / 32, HID / 32);
    wt_split_kernel<<<tg, tb>>>(W);

    cudaFuncSetAttribute(gemm_f16x3_kernel,
                         cudaFuncAttributeMaxDynamicSharedMemorySize, GEMM_SMEM);
    gemm_f16x3_kernel<<<GEMM_GRID, 256, GEMM_SMEM>>>();

    cudaFuncSetAttribute(attn_tc_kernel,
                         cudaFuncAttributeMaxDynamicSharedMemorySize, ATTN_SMEM);
    dim3 ga(SEQ / 64, BATCH);
    attn_tc_kernel<<<ga, NTHR, ATTN_SMEM>>>(repr, out);
}

// round 16
// speedup vs baseline: 1.1323x; 1.1323x over previous
#include <cuda_runtime.h>
#include <cuda_fp16.h>
#include <cstdint>

#define BATCH 8
#define SEQ   2048
#define HID   1024
#define M_TOT (BATCH * SEQ)        // 16384
#define WHALF 64
#define NEG_INF -1e9f

// Scratch (__device__ globals; no allocation allowed) — all fp16 hi/lo splits
__device__ __align__(16) __half g_qw_hi[(size_t)M_TOT * HID];
__device__ __align__(16) __half g_qw_lo[(size_t)M_TOT * HID];
__device__ __align__(16) __half g_a_hi[(size_t)M_TOT * HID];   // also V in phase 3
__device__ __align__(16) __half g_a_lo[(size_t)M_TOT * HID];
__device__ __align__(16) __half g_wt_hi[(size_t)HID * HID];
__device__ __align__(16) __half g_wt_lo[(size_t)HID * HID];

// ---------------------------------------------------------------------------
// PTX helpers (architecture-neutral, sm_80-level)
// ---------------------------------------------------------------------------
__device__ __forceinline__ uint32_t smem_u32(const void* p) {
    uint32_t a;
    asm("{ .reg .u64 t; cvta.to.shared.u64 t, %1; cvt.u32.u64 %0, t; }" : "=r"(a) : "l"(p));
    return a;
}

#define CP_ASYNC16(dst_u32, src_ptr) \
    asm volatile("cp.async.cg.shared.global [%0], [%1], 16;" :: "r"(dst_u32), "l"(src_ptr))
#define CP_COMMIT() asm volatile("cp.async.commit_group;" ::: "memory")
#define CP_WAIT(n)  asm volatile("cp.async.wait_group %0;" :: "n"(n) : "memory")

#define LDMATRIX_X4(r0, r1, r2, r3, addr) \
    asm volatile("ldmatrix.sync.aligned.m8n8.x4.shared.b16 {%0,%1,%2,%3}, [%4];" \
                 : "=r"(r0), "=r"(r1), "=r"(r2), "=r"(r3) : "r"(addr))
#define LDMATRIX_X4_TRANS(r0, r1, r2, r3, addr) \
    asm volatile("ldmatrix.sync.aligned.m8n8.x4.trans.shared.b16 {%0,%1,%2,%3}, [%4];" \
                 : "=r"(r0), "=r"(r1), "=r"(r2), "=r"(r3) : "r"(addr))

#define MMA_F16(d, a, b0v, b1v) \
    asm volatile("mma.sync.aligned.m16n8k16.row.col.f32.f16.f16.f32 " \
                 "{%0,%1,%2,%3},{%4,%5,%6,%7},{%8,%9},{%0,%1,%2,%3};" \
                 : "+f"((d)[0]), "+f"((d)[1]), "+f"((d)[2]), "+f"((d)[3]) \
                 : "r"((a)[0]), "r"((a)[1]), "r"((a)[2]), "r"((a)[3]), \
                   "r"(b0v), "r"(b1v))

// 64B-pitch XOR swizzle: row stride 64 B, segs (16 B) permuted by row.
// Conflict-optimal for 16-row x 2-half ldmatrix address patterns.
#define SWZ(row, seg) \
    ((uint32_t)((row) * 64 + ((((seg) ^ (((row) >> 1) & 3))) << 4)))

__device__ __forceinline__ void split_pack_h(float a, float b, uint32_t& hi, uint32_t& lo) {
    __half ha = __float2half_rn(a);
    __half hb = __float2half_rn(b);
    __half la = __float2half_rn(a - __half2float(ha));
    __half lb = __float2half_rn(b - __half2float(hb));
    __half hp[2] = {ha, hb};
    __half lp[2] = {la, lb};
    hi = *(uint32_t*)hp;
    lo = *(uint32_t*)lp;
}

// ---------------------------------------------------------------------------
// Prep 1: repr -> a_hi/a_lo (fp16)
// ---------------------------------------------------------------------------
__global__ __launch_bounds__(256) void repr_split_kernel(const float* __restrict__ r) {
    size_t i = ((size_t)blockIdx.x * 256 + threadIdx.x) * 4;
    float4 v = *(const float4*)&r[i];
    uint32_t h0, l0, h1, l1;
    split_pack_h(v.x, v.y, h0, l0);
    split_pack_h(v.z, v.w, h1, l1);
    uint2 hh = {h0, h1}, ll = {l0, l1};
    *(uint2*)&g_a_hi[i] = hh;
    *(uint2*)&g_a_lo[i] = ll;
}

// ---------------------------------------------------------------------------
// Prep 2: W[k][n] -> Wt_hi/Wt_lo [n][k] (fp16)
// ---------------------------------------------------------------------------
__global__ void wt_split_kernel(const float* __restrict__ W) {
    __shared__ float t[32][33];
    int bx = blockIdx.x * 32, by = blockIdx.y * 32;
    int x = threadIdx.x, y0 = threadIdx.y;
#pragma unroll
    for (int i = 0; i < 32; i += 8)
        t[y0 + i][x] = W[(size_t)(by + y0 + i) * HID + bx + x];
    __syncthreads();
#pragma unroll
    for (int i = 0; i < 32; i += 8) {
        float v = t[x][y0 + i];
        size_t o = (size_t)(bx + y0 + i) * HID + by + x;
        __half hi = __float2half_rn(v);
        g_wt_hi[o] = hi;
        g_wt_lo[o] = __float2half_rn(v - __half2float(hi));
    }
}

// ---------------------------------------------------------------------------
// Kernel 1: fp16x3 GEMM  QW = repr @ W — 3-stage swizzled pipeline
// Stage (32 KB): Ah[128x64B] | Al | Bh | Bl
// ---------------------------------------------------------------------------
#define KB   32
#define NCH  (HID / KB)
#define T64_B   8192                   // one 128-row x 64B tile
#define STG_B   (4 * T64_B)            // 32768
#define GEMM_SMEM (3 * STG_B)          // 98304

__global__ __launch_bounds__(256, 2) void gemm_f16x3_kernel() {
    extern __shared__ char sm[];
    const uint32_t smBase = smem_u32(sm);

    const int tid  = threadIdx.x;
    const int w    = tid >> 5;
    const int lane = tid & 31;
    const int wm   = w & 1;
    const int wn   = w >> 1;
    const int m0   = blockIdx.y * 128;
    const int n0   = blockIdx.x * 128;

    float acc[4][4][4];
#pragma unroll
    for (int i = 0; i < 4; i++)
#pragma unroll
        for (int j = 0; j < 4; j++)
#pragma unroll
            for (int q = 0; q < 4; q++) acc[i][j][q] = 0.f;

    // loader geometry (two slots per thread; offsets constant)
    const int r0 = tid >> 2,          s0 = tid & 3;
    const int r1 = (tid + 256) >> 2,  s1 = (tid + 256) & 3;
    const uint32_t d0 = SWZ(r0, s0);
    const uint32_t d1 = SWZ(r1, s1);

    auto load_chunk = [&](uint32_t sb, int c) {
        const int k0 = c * KB;
        size_t ia0 = (size_t)(m0 + r0) * HID + k0 + s0 * 8;
        size_t ia1 = (size_t)(m0 + r1) * HID + k0 + s1 * 8;
        size_t ib0 = (size_t)(n0 + r0) * HID + k0 + s0 * 8;
        size_t ib1 = (size_t)(n0 + r1) * HID + k0 + s1 * 8;
        CP_ASYNC16(sb + d0,             &g_a_hi[ia0]);
        CP_ASYNC16(sb + T64_B + d0,     &g_a_lo[ia0]);
        CP_ASYNC16(sb + 2 * T64_B + d0, &g_wt_hi[ib0]);
        CP_ASYNC16(sb + 3 * T64_B + d0, &g_wt_lo[ib0]);
        CP_ASYNC16(sb + d1,             &g_a_hi[ia1]);
        CP_ASYNC16(sb + T64_B + d1,     &g_a_lo[ia1]);
        CP_ASYNC16(sb + 2 * T64_B + d1, &g_wt_hi[ib1]);
        CP_ASYNC16(sb + 3 * T64_B + d1, &g_wt_lo[ib1]);
    };

    load_chunk(smBase, 0);             CP_COMMIT();
    load_chunk(smBase + STG_B, 1);     CP_COMMIT();

    int s_cur = 0, s_nxt = 2;          // compute stage, fill stage
    for (int c = 0; c < NCH; c++) {
        CP_WAIT(1);                    // chunk c resident (c+1 may be in flight)
        __syncthreads();               // stage s_nxt's old readers done
        if (c + 2 < NCH) {
            load_chunk(smBase + (uint32_t)(s_nxt * STG_B), c + 2);
            CP_COMMIT();
        }

        const uint32_t sb = smBase + (uint32_t)(s_cur * STG_B);
#pragma unroll
        for (int ks = 0; ks < 2; ks++) {
            uint32_t ah[4][4], al[4][4], bh[2][4], bl[2][4];
            const int segb = 2 * ks + (lane >> 4);
#pragma unroll
            for (int mt = 0; mt < 4; mt++) {
                int row = wm * 64 + mt * 16 + (lane & 15);
                uint32_t ra = sb + SWZ(row, segb);
                LDMATRIX_X4(ah[mt][0], ah[mt][1], ah[mt][2], ah[mt][3], ra);
                LDMATRIX_X4(al[mt][0], al[mt][1], al[mt][2], al[mt][3], ra + T64_B);
            }
#pragma unroll
            for (int np = 0; np < 2; np++) {
                int row = wn * 32 + np * 16 + (lane & 15);
                uint32_t rb = sb + 2 * T64_B + SWZ(row, segb);
                LDMATRIX_X4(bh[np][0], bh[np][1], bh[np][2], bh[np][3], rb);
                LDMATRIX_X4(bl[np][0], bl[np][1], bl[np][2], bl[np][3], rb + T64_B);
            }
#pragma unroll
            for (int mt = 0; mt < 4; mt++)
#pragma unroll
                for (int nt = 0; nt < 4; nt++) {
                    const int np = nt >> 1, hp = nt & 1;
                    MMA_F16(acc[mt][nt], ah[mt], bh[np][hp], bh[np][hp + 2]);
                }
#pragma unroll
            for (int mt = 0; mt < 4; mt++)
#pragma unroll
                for (int nt = 0; nt < 4; nt++) {
                    const int np = nt >> 1, hp = nt & 1;
                    MMA_F16(acc[mt][nt], ah[mt], bl[np][hp], bl[np][hp + 2]);
                }
#pragma unroll
            for (int mt = 0; mt < 4; mt++)
#pragma unroll
                for (int nt = 0; nt < 4; nt++) {
                    const int np = nt >> 1, hp = nt & 1;
                    MMA_F16(acc[mt][nt], al[mt], bh[np][hp], bh[np][hp + 2]);
                }
        }
        s_cur = s_cur == 2 ? 0 : s_cur + 1;
        s_nxt = s_nxt == 2 ? 0 : s_nxt + 1;
    }

    const int gid = lane >> 2, tig = lane & 3;
#pragma unroll
    for (int mt = 0; mt < 4; mt++) {
#pragma unroll
        for (int nt = 0; nt < 4; nt++) {
#pragma unroll
            for (int h = 0; h < 2; h++) {
                int r  = m0 + wm * 64 + mt * 16 + gid + h * 8;
                int cc = n0 + wn * 32 + nt * 8 + tig * 2;
                uint32_t hp2, lp2;
                split_pack_h(acc[mt][nt][h * 2 + 0], acc[mt][nt][h * 2 + 1], hp2, lp2);
                *(uint32_t*)&g_qw_hi[(size_t)r * HID + cc] = hp2;
                *(uint32_t*)&g_qw_lo[(size_t)r * HID + cc] = lp2;
            }
        }
    }
}

// ---------------------------------------------------------------------------
// Kernel 2: tensor-core windowed attention — 64-query / 128-thread CTAs,
// warp-private bands, occ 2; phase-1 3-stage swizzled pipeline; V 2-stage
// with stage-0 prefetch during the last phase-1 chunk.
// Stage (32 KB): Qh[64x64B] | Ql | Kh[192x64B] | Kl
// ---------------------------------------------------------------------------
#define NTHR   128
#define AQ64_B (64 * 64)               // 4096
#define AK64_B (192 * 64)              // 12288
#define A_STG3 (2 * AQ64_B + 2 * AK64_B)  // 32768
#define DCW 64
#define NDC (HID / DCW)                // 16
#define VP2 72                         // fp16 pitch for 64-col V rows (144 B)
#define V_B2 (192 * VP2 * 2)           // 27648 per stage
#define ATTN_SMEM (3 * A_STG3)         // 98304 (V stages at 0 / V_B2)

__global__ __launch_bounds__(NTHR, 2) void attn_tc_kernel(
    const float* __restrict__ repr, float* __restrict__ out)
{
    extern __shared__ char sm[];
    const uint32_t smb = smem_u32(sm);

    const int tid  = threadIdx.x;
    const int wm   = tid >> 5;          // 0..3: row group AND band owner
    const int lane = tid & 31;
    const int gid  = lane >> 2, tig = lane & 3;
    const int bc0  = wm * 16;           // warp's band-col base (rel. to k0)

    const int b  = blockIdx.y;
    const int q0 = blockIdx.x * 64;
    const int k0 = q0 - WHALF;
    const size_t rowbase = (size_t)b * SEQ;

    // ---------------- Phase 1: S = Q·K^T (frags in regs) -----------------
    auto load_qk = [&](uint32_t sb, int c) {
        const int kd = c * KB;
#pragma unroll
        for (int rep = 0; rep < 2; rep++) {          // Q: 64 rows x 4 segs
            int idx = tid + rep * NTHR;
            int row = idx >> 2, seg = idx & 3;
            uint32_t off = SWZ(row, seg);
            size_t ga = (rowbase + q0 + row) * HID + kd + seg * 8;
            CP_ASYNC16(sb + off,          &g_qw_hi[ga]);
            CP_ASYNC16(sb + AQ64_B + off, &g_qw_lo[ga]);
        }
#pragma unroll
        for (int rep = 0; rep < 6; rep++) {          // K: 192 rows x 4 segs
            int idx = tid + rep * NTHR;
            int row = idx >> 2, seg = idx & 3;
            int j = k0 + row;
            j = j < 0 ? 0 : (j >= SEQ ? SEQ - 1 : j);   // clamp; masked later
            uint32_t off = SWZ(row, seg);
            size_t ga = (rowbase + j) * HID + kd + seg * 8;
            CP_ASYNC16(sb + 2 * AQ64_B + off,          &g_a_hi[ga]);
            CP_ASYNC16(sb + 2 * AQ64_B + AK64_B + off, &g_a_lo[ga]);
        }
    };
    auto load_v = [&](int stage, int d) {
        const int d0 = d * DCW;
        const uint32_t sb = smb + stage * V_B2;
#pragma unroll
        for (int rep = 0; rep < 12; rep++) {
            int idx = tid + rep * NTHR;
            int vr = idx >> 3, seg = idx & 7;
            int j = k0 + vr;
            j = j < 0 ? 0 : (j >= SEQ ? SEQ - 1 : j);   // clamp; P=0 there
            uint32_t off = (uint32_t)(vr * (VP2 * 2) + seg * 16);
            CP_ASYNC16(sb + off, &g_a_hi[(rowbase + j) * HID + d0 + seg * 8]);
        }
    };

    float acc[18][4];
#pragma unroll
    for (int i = 0; i < 18; i++)
#pragma unroll
        for (int q = 0; q < 4; q++) acc[i][q] = 0.f;

    load_qk(smb, 0);           CP_COMMIT();
    load_qk(smb + A_STG3, 1);  CP_COMMIT();

    int s_cur = 0, s_nxt = 2;
    for (int c = 0; c < NCH; c++) {
        CP_WAIT(1);
        __syncthreads();
        if (c + 2 < NCH) {
            load_qk(smb + (uint32_t)(s_nxt * A_STG3), c + 2);
            CP_COMMIT();
        } else if (c == NCH - 1) {
            // prefetch V stage 0 (0..27648 within dead stage region)
            load_v(0, 0);
            CP_COMMIT();
        }

        const uint32_t sb = smb + (uint32_t)(s_cur * A_STG3);
#pragma unroll
        for (int ks = 0; ks < 2; ks++) {
            const int segb = 2 * ks + (lane >> 4);
            uint32_t ah[4], al[4];
            uint32_t ra = sb + SWZ(wm * 16 + (lane & 15), segb);
            LDMATRIX_X4(ah[0], ah[1], ah[2], ah[3], ra);
            LDMATRIX_X4(al[0], al[1], al[2], al[3], ra + AQ64_B);
#pragma unroll
            for (int p = 0; p < 9; p++) {
                uint32_t bh[4], bl[4];
                uint32_t rb = sb + 2 * AQ64_B + SWZ(bc0 + p * 16 + (lane & 15), segb);
                LDMATRIX_X4(bh[0], bh[1], bh[2], bh[3], rb);
                LDMATRIX_X4(bl[0], bl[1], bl[2], bl[3], rb + AK64_B);
#pragma unroll
                for (int hp = 0; hp < 2; hp++) {
                    int nt = p * 2 + hp;
                    MMA_F16(acc[nt], ah, bh[hp], bh[hp + 2]);
                    MMA_F16(acc[nt], ah, bl[hp], bl[hp + 2]);
                    MMA_F16(acc[nt], al, bh[hp], bh[hp + 2]);
                }
            }
        }
        s_cur = s_cur == 2 ? 0 : s_cur + 1;
        s_nxt = s_nxt == 2 ? 0 : s_nxt + 1;
    }

    // ---------------- Phase 2: warp-local softmax -------------------------
#pragma unroll
    for (int nt = 0; nt < 18; nt++) {
#pragma unroll
        for (int h = 0; h < 2; h++) {
            int row = wm * 16 + gid + h * 8;
#pragma unroll
            for (int e = 0; e < 2; e++) {
                int bc = bc0 + nt * 8 + tig * 2 + e;
                int j = k0 + bc, dr = bc - row;
                if (!((j >= 0) && (j < SEQ) && (dr >= 0) && (dr <= 2 * WHALF)))
                    acc[nt][h * 2 + e] = NEG_INF;
            }
        }
    }

    float mrow[2] = {NEG_INF, NEG_INF};
#pragma unroll
    for (int nt = 0; nt < 18; nt++) {
        mrow[0] = fmaxf(mrow[0], fmaxf(acc[nt][0], acc[nt][1]));
        mrow[1] = fmaxf(mrow[1], fmaxf(acc[nt][2], acc[nt][3]));
    }
#pragma unroll
    for (int h = 0; h < 2; h++) {
        mrow[h] = fmaxf(mrow[h], __shfl_xor_sync(0xffffffffu, mrow[h], 1));
        mrow[h] = fmaxf(mrow[h], __shfl_xor_sync(0xffffffffu, mrow[h], 2));
    }

    float srow[2] = {0.f, 0.f};
#pragma unroll
    for (int nt = 0; nt < 18; nt++) {
#pragma unroll
        for (int h = 0; h < 2; h++) {
#pragma unroll
            for (int e = 0; e < 2; e++) {
                float ex = __expf(acc[nt][h * 2 + e] - mrow[h]);
                acc[nt][h * 2 + e] = ex;
                srow[h] += ex;
            }
        }
    }
#pragma unroll
    for (int h = 0; h < 2; h++) {
        srow[h] += __shfl_xor_sync(0xffffffffu, srow[h], 1);
        srow[h] += __shfl_xor_sync(0xffffffffu, srow[h], 2);
    }
    const float inv0 = 1.f / srow[0];
    const float inv1 = 1.f / srow[1];

    // P hi/lo fp16 fragments (9 k-tiles, warp-private band)
    uint32_t ph[9][4], pl[9][4];
#pragma unroll
    for (int t = 0; t < 9; t++) {
        split_pack_h(acc[2 * t][0] * inv0,     acc[2 * t][1] * inv0,     ph[t][0], pl[t][0]);
        split_pack_h(acc[2 * t][2] * inv1,     acc[2 * t][3] * inv1,     ph[t][1], pl[t][1]);
        split_pack_h(acc[2 * t + 1][0] * inv0, acc[2 * t + 1][1] * inv0, ph[t][2], pl[t][2]);
        split_pack_h(acc[2 * t + 1][2] * inv1, acc[2 * t + 1][3] * inv1, ph[t][3], pl[t][3]);
    }

    // ---------------- Phase 3: O = P·V (fp16, 2-term), dc=64 --------------
    for (int d = 0; d < NDC; d++) {
        CP_WAIT(0);
        __syncthreads();
        if (d + 1 < NDC) {
            load_v((d + 1) & 1, d + 1);
            CP_COMMIT();
        }

        const uint32_t vb = smb + (d & 1) * V_B2;

        float o[8][4];
#pragma unroll
        for (int i = 0; i < 8; i++)
#pragma unroll
            for (int q = 0; q < 4; q++) o[i][q] = 0.f;

#pragma unroll
        for (int t = 0; t < 9; t++) {
            const int brow = bc0 + t * 16;
            uint32_t vh[4][4];
#pragma unroll
            for (int p = 0; p < 4; p++) {
                uint32_t rb = vb + (uint32_t)((brow + (lane & 15)) * (VP2 * 2)) +
                              (uint32_t)((p * 16 + ((lane >> 4) << 3)) * 2);
                LDMATRIX_X4_TRANS(vh[p][0], vh[p][1], vh[p][2], vh[p][3], rb);
            }
#pragma unroll
            for (int p = 0; p < 4; p++) {
                MMA_F16(o[p * 2 + 0], ph[t], vh[p][0], vh[p][1]);
                MMA_F16(o[p * 2 + 1], ph[t], vh[p][2], vh[p][3]);
            }
#pragma unroll
            for (int p = 0; p < 4; p++) {
                MMA_F16(o[p * 2 + 0], pl[t], vh[p][0], vh[p][1]);
                MMA_F16(o[p * 2 + 1], pl[t], vh[p][2], vh[p][3]);
            }
        }

        // direct epilogue: out = repr + relu(o)
#pragma unroll
        for (int nt = 0; nt < 8; nt++) {
#pragma unroll
            for (int h = 0; h < 2; h++) {
                int gr = q0 + wm * 16 + gid + h * 8;
                int gc = d * DCW + nt * 8 + tig * 2;
                const float2 rv = *(const float2*)&repr[(rowbase + gr) * HID + gc];
                float2 ov;
                ov.x = rv.x + fmaxf(o[nt][h * 2 + 0], 0.f);
                ov.y = rv.y + fmaxf(o[nt][h * 2 + 1], 0.f);
                *(float2*)&out[(rowbase + gr) * HID + gc] = ov;
            }
        }
    }
}

// ---------------------------------------------------------------------------
extern "C" void kernel_launch(void* const* d_in, const int* in_sizes, int n_in,
                              void* d_out, int out_size)
{
    (void)in_sizes; (void)n_in; (void)out_size;
    const float* repr = (const float*)d_in[0];
    const float* W    = (const float*)d_in[1];
    float* out        = (float*)d_out;

    repr_split_kernel<<<(M_TOT * HID) / (256 * 4), 256>>>(repr);
    dim3 tb(32, 8), tg(HID / 32, HID / 32);
    wt_split_kernel<<<tg, tb>>>(W);

    cudaFuncSetAttribute(gemm_f16x3_kernel,
                         cudaFuncAttributeMaxDynamicSharedMemorySize, GEMM_SMEM);
    dim3 gg(HID / 128, M_TOT / 128);
    gemm_f16x3_kernel<<<gg, 256, GEMM_SMEM>>>();

    cudaFuncSetAttribute(attn_tc_kernel,
                         cudaFuncAttributeMaxDynamicSharedMemorySize, ATTN_SMEM);
    dim3 ga(SEQ / 64, BATCH);
    attn_tc_kernel<<<ga, NTHR, ATTN_SMEM>>>(repr, out);
}